// round 3
// baseline (speedup 1.0000x reference)
#include <cuda_runtime.h>
#include <cuda_bf16.h>

// Problem constants (WordSmoothCriterion: B=4, T=2048, V=32000, NNZ=801)
#define NROWS 8192
#define VDIM  32000
#define NNZ   801
#define TAU   0.8f
#define RARE  1.0f
#define ALPHA 0.7f

// Scratch (device globals — allocation-free)
__device__ float g_smooth[NROWS];   // per-row sum(g*sim)
__device__ float g_ml[NROWS];       // per-row lp[target]*mask
__device__ float g_maskv[NROWS];    // per-row mask
__device__ unsigned int g_count = 0;  // completion counter (self-resetting)

// Plain coherent global load — guaranteed NOT the .nc/CONSTANT (LDG.E.CI) path,
// so DRAM fills should be 32B-sector granular instead of 128B-line promoted.
__device__ __forceinline__ float ld_plain(const float* p) {
    float v;
    asm("ld.global.f32 %0, [%1];" : "=f"(v) : "l"(p));
    return v;
}

// ---------------------------------------------------------------------------
// Fused kernel: per-row partials + last-block final reduction.
// One CTA per row, 256 threads.
// ---------------------------------------------------------------------------
__global__ __launch_bounds__(256, 8)
void ws_fused_kernel(const float* __restrict__ logp,
                     const float* __restrict__ mask,
                     const float* __restrict__ sim_values,
                     const float* __restrict__ idf_values,
                     const int*   __restrict__ target,
                     const int*   __restrict__ sim_cols,
                     float*       __restrict__ out)
{
    const int n = blockIdx.x;
    const int r = target[n];

    const float* __restrict__ sv = sim_values + (size_t)r * NNZ;
    const float* __restrict__ iv = idf_values + (size_t)r * NNZ;
    const int*   __restrict__ sc = sim_cols   + (size_t)r * NNZ;
    const float* __restrict__ lp = logp       + (size_t)n * VDIM;

    const float inv_tau = 1.0f / TAU;

    float sum_v  = 0.0f;   // sum of vals
    float sum_gv = 0.0f;   // sum of vals * gathered logp

    // 801 elems / 256 threads -> up to 4 iterations.
    // Contiguous streams use evict-first (__ldcs): consumed once, keep L2 for
    // the gather lines. Gather uses the coherent path (32B sector fills).
    #pragma unroll 4
    for (int j = threadIdx.x; j < NNZ; j += 256) {
        float s = __ldcs(sv + j);
        float d = __ldcs(iv + j);
        int   c = __ldcs(sc + j);
        float g = ld_plain(lp + c);                    // scattered 4B gather
        float v = (s - 1.0f - TAU * RARE * d) * inv_tau;
        float val = __expf(__expf(v) * inv_tau);       // exp(exp(v/tau)/tau)
        sum_v  += val;
        sum_gv += val * g;
    }

    // -------- block reduction of (sum_v, sum_gv) --------
    #pragma unroll
    for (int o = 16; o > 0; o >>= 1) {
        sum_v  += __shfl_down_sync(0xffffffffu, sum_v,  o);
        sum_gv += __shfl_down_sync(0xffffffffu, sum_gv, o);
    }
    __shared__ float s_v[8], s_gv[8];
    __shared__ bool  s_last;
    const int warp = threadIdx.x >> 5;
    const int lane = threadIdx.x & 31;
    if (lane == 0) { s_v[warp] = sum_v; s_gv[warp] = sum_gv; }
    __syncthreads();
    if (warp == 0) {
        float a = (lane < 8) ? s_v[lane]  : 0.0f;
        float b = (lane < 8) ? s_gv[lane] : 0.0f;
        #pragma unroll
        for (int o = 4; o > 0; o >>= 1) {
            a += __shfl_down_sync(0xffffffffu, a, o);
            b += __shfl_down_sync(0xffffffffu, b, o);
        }
        if (lane == 0) {
            float m = mask[n];
            g_smooth[n] = b / a;                        // sum(g * sim) for row n
            g_ml[n]     = ld_plain(lp + r) * m;         // lp[n, target[n]] * m[n]
            g_maskv[n]  = m;
            __threadfence();                            // make partials visible
            unsigned int old = atomicAdd(&g_count, 1u);
            s_last = (old == (unsigned int)(gridDim.x - 1));
        }
    }
    __syncthreads();

    // -------- last CTA performs the final (deterministic) reduction --------
    if (s_last) {
        double d_sm = 0.0, d_ml = 0.0, d_m = 0.0;
        // fixed strided order -> deterministic; data is L2-warm
        for (int i = threadIdx.x; i < NROWS; i += 256) {
            d_sm += (double)g_smooth[i];
            d_ml += (double)g_ml[i];
            d_m  += (double)g_maskv[i];
        }
        #pragma unroll
        for (int o = 16; o > 0; o >>= 1) {
            d_sm += __shfl_down_sync(0xffffffffu, d_sm, o);
            d_ml += __shfl_down_sync(0xffffffffu, d_ml, o);
            d_m  += __shfl_down_sync(0xffffffffu, d_m,  o);
        }
        __shared__ double sh[3][8];
        if (lane == 0) { sh[0][warp] = d_sm; sh[1][warp] = d_ml; sh[2][warp] = d_m; }
        __syncthreads();
        if (warp == 0) {
            d_sm = (lane < 8) ? sh[0][lane] : 0.0;
            d_ml = (lane < 8) ? sh[1][lane] : 0.0;
            d_m  = (lane < 8) ? sh[2][lane] : 0.0;
            #pragma unroll
            for (int o = 4; o > 0; o >>= 1) {
                d_sm += __shfl_down_sync(0xffffffffu, d_sm, o);
                d_ml += __shfl_down_sync(0xffffffffu, d_ml, o);
                d_m  += __shfl_down_sync(0xffffffffu, d_m,  o);
            }
            if (lane == 0) {
                double smooth_loss = -d_sm / d_m;
                double ml_loss     = -d_ml / d_m;
                out[0] = (float)((double)ALPHA * smooth_loss
                                 + (1.0 - (double)ALPHA) * ml_loss);
                g_count = 0;   // reset for next graph replay
            }
        }
    }
}

// ---------------------------------------------------------------------------
extern "C" void kernel_launch(void* const* d_in, const int* in_sizes, int n_in,
                              void* d_out, int out_size)
{
    const float* logp       = (const float*)d_in[0];
    const float* mask       = (const float*)d_in[1];
    const float* sim_values = (const float*)d_in[2];
    const float* idf_values = (const float*)d_in[3];
    const int*   target     = (const int*)  d_in[4];
    const int*   sim_cols   = (const int*)  d_in[5];
    float*       out        = (float*)d_out;

    ws_fused_kernel<<<NROWS, 256>>>(logp, mask, sim_values, idf_values,
                                    target, sim_cols, out);
}

// round 4
// speedup vs baseline: 1.0524x; 1.0524x over previous
#include <cuda_runtime.h>
#include <cuda_bf16.h>

// Problem constants (WordSmoothCriterion: B=4, T=2048, V=32000, NNZ=801)
#define NROWS 8192
#define VDIM  32000
#define NNZ   801
#define TAU   0.8f
#define RARE  1.0f
#define ALPHA 0.7f

// Scratch (device globals — allocation-free)
__device__ float g_smooth[NROWS];   // per-row sum(g*sim)
__device__ float g_ml[NROWS];       // per-row lp[target]*mask
__device__ float g_maskv[NROWS];    // per-row mask
__device__ unsigned int g_count = 0;  // completion counter (self-resetting)

// L2-only load (bypass L1 allocation). Diagnostic for DRAM fill granularity:
// if the L1-allocating path is what promotes fills to 128B lines, .cg should
// fetch only the needed 32B sectors.
__device__ __forceinline__ float ld_cg(const float* p) {
    float v;
    asm("ld.global.cg.f32 %0, [%1];" : "=f"(v) : "l"(p));
    return v;
}

// ---------------------------------------------------------------------------
// Fused kernel: per-row partials + last-block final reduction.
// One CTA per row, 256 threads.
// ---------------------------------------------------------------------------
__global__ __launch_bounds__(256, 8)
void ws_fused_kernel(const float* __restrict__ logp,
                     const float* __restrict__ mask,
                     const float* __restrict__ sim_values,
                     const float* __restrict__ idf_values,
                     const int*   __restrict__ target,
                     const int*   __restrict__ sim_cols,
                     float*       __restrict__ out)
{
    const int n = blockIdx.x;
    const int r = target[n];

    const float* __restrict__ sv = sim_values + (size_t)r * NNZ;
    const float* __restrict__ iv = idf_values + (size_t)r * NNZ;
    const int*   __restrict__ sc = sim_cols   + (size_t)r * NNZ;
    const float* __restrict__ lp = logp       + (size_t)n * VDIM;

    const float inv_tau = 1.0f / TAU;

    float sum_v  = 0.0f;   // sum of vals
    float sum_gv = 0.0f;   // sum of vals * gathered logp

    // Contiguous streams: default caching loads (L2 dedups rows shared by
    // duplicate targets). Gather: .cg L2-only path.
    #pragma unroll 4
    for (int j = threadIdx.x; j < NNZ; j += 256) {
        float s = sv[j];
        float d = iv[j];
        int   c = sc[j];
        float g = ld_cg(lp + c);                       // scattered 4B gather
        float v = (s - 1.0f - TAU * RARE * d) * inv_tau;
        float val = __expf(__expf(v) * inv_tau);       // exp(exp(v/tau)/tau)
        sum_v  += val;
        sum_gv += val * g;
    }

    // -------- block reduction of (sum_v, sum_gv) --------
    #pragma unroll
    for (int o = 16; o > 0; o >>= 1) {
        sum_v  += __shfl_down_sync(0xffffffffu, sum_v,  o);
        sum_gv += __shfl_down_sync(0xffffffffu, sum_gv, o);
    }
    __shared__ float s_v[8], s_gv[8];
    __shared__ bool  s_last;
    const int warp = threadIdx.x >> 5;
    const int lane = threadIdx.x & 31;
    if (lane == 0) { s_v[warp] = sum_v; s_gv[warp] = sum_gv; }
    __syncthreads();
    if (warp == 0) {
        float a = (lane < 8) ? s_v[lane]  : 0.0f;
        float b = (lane < 8) ? s_gv[lane] : 0.0f;
        #pragma unroll
        for (int o = 4; o > 0; o >>= 1) {
            a += __shfl_down_sync(0xffffffffu, a, o);
            b += __shfl_down_sync(0xffffffffu, b, o);
        }
        if (lane == 0) {
            float m = mask[n];
            g_smooth[n] = b / a;                        // sum(g * sim) for row n
            g_ml[n]     = lp[r] * m;                    // lp[n, target[n]] * m[n]
            g_maskv[n]  = m;
            __threadfence();                            // make partials visible
            unsigned int old = atomicAdd(&g_count, 1u);
            s_last = (old == (unsigned int)(gridDim.x - 1));
        }
    }
    __syncthreads();

    // -------- last CTA performs the final (deterministic) reduction --------
    if (s_last) {
        double d_sm = 0.0, d_ml = 0.0, d_m = 0.0;
        // fixed strided order -> deterministic; data is L2-warm
        for (int i = threadIdx.x; i < NROWS; i += 256) {
            d_sm += (double)g_smooth[i];
            d_ml += (double)g_ml[i];
            d_m  += (double)g_maskv[i];
        }
        #pragma unroll
        for (int o = 16; o > 0; o >>= 1) {
            d_sm += __shfl_down_sync(0xffffffffu, d_sm, o);
            d_ml += __shfl_down_sync(0xffffffffu, d_ml, o);
            d_m  += __shfl_down_sync(0xffffffffu, d_m,  o);
        }
        __shared__ double sh[3][8];
        if (lane == 0) { sh[0][warp] = d_sm; sh[1][warp] = d_ml; sh[2][warp] = d_m; }
        __syncthreads();
        if (warp == 0) {
            d_sm = (lane < 8) ? sh[0][lane] : 0.0;
            d_ml = (lane < 8) ? sh[1][lane] : 0.0;
            d_m  = (lane < 8) ? sh[2][lane] : 0.0;
            #pragma unroll
            for (int o = 4; o > 0; o >>= 1) {
                d_sm += __shfl_down_sync(0xffffffffu, d_sm, o);
                d_ml += __shfl_down_sync(0xffffffffu, d_ml, o);
                d_m  += __shfl_down_sync(0xffffffffu, d_m,  o);
            }
            if (lane == 0) {
                double smooth_loss = -d_sm / d_m;
                double ml_loss     = -d_ml / d_m;
                out[0] = (float)((double)ALPHA * smooth_loss
                                 + (1.0 - (double)ALPHA) * ml_loss);
                g_count = 0;   // reset for next graph replay
            }
        }
    }
}

// ---------------------------------------------------------------------------
extern "C" void kernel_launch(void* const* d_in, const int* in_sizes, int n_in,
                              void* d_out, int out_size)
{
    const float* logp       = (const float*)d_in[0];
    const float* mask       = (const float*)d_in[1];
    const float* sim_values = (const float*)d_in[2];
    const float* idf_values = (const float*)d_in[3];
    const int*   target     = (const int*)  d_in[4];
    const int*   sim_cols   = (const int*)  d_in[5];
    float*       out        = (float*)d_out;

    ws_fused_kernel<<<NROWS, 256>>>(logp, mask, sim_values, idf_values,
                                    target, sim_cols, out);
}

// round 6
// speedup vs baseline: 1.1111x; 1.0558x over previous
#include <cuda_runtime.h>
#include <cuda_bf16.h>

// Problem constants (WordSmoothCriterion: B=4, T=2048, V=32000, NNZ=801)
#define NROWS 8192
#define VDIM  32000
#define NNZ   801
#define TAU   0.8f
#define RARE  1.0f
#define ALPHA 0.7f

// Scratch (device globals — allocation-free)
__device__ float g_smooth[NROWS];   // per-row sum(g*sim)
__device__ float g_ml[NROWS];       // per-row lp[target]*mask
__device__ float g_maskv[NROWS];    // per-row mask
__device__ unsigned int g_count = 0;  // completion counter (self-resetting)

// ---------------------------------------------------------------------------
// Fused kernel: per-row partials + last-block final reduction.
// One CTA per row, 256 threads. Loop fully peeled to front-batch loads:
// 4 independent cols loads -> 4 independent gathers in flight per thread.
// ---------------------------------------------------------------------------
__global__ __launch_bounds__(256, 6)
void ws_fused_kernel(const float* __restrict__ logp,
                     const float* __restrict__ mask,
                     const float* __restrict__ sim_values,
                     const float* __restrict__ idf_values,
                     const int*   __restrict__ target,
                     const int*   __restrict__ sim_cols,
                     float*       __restrict__ out)
{
    const int n = blockIdx.x;
    const int r = target[n];

    const float* __restrict__ sv = sim_values + (size_t)r * NNZ;
    const float* __restrict__ iv = idf_values + (size_t)r * NNZ;
    const int*   __restrict__ sc = sim_cols   + (size_t)r * NNZ;
    const float* __restrict__ lp = logp       + (size_t)n * VDIM;

    const float inv_tau = 1.0f / TAU;
    const int   tid = threadIdx.x;

    // j0..j2 always in range (max 767 < 801); j3 needs the bound check.
    const int  j0 = tid, j1 = tid + 256, j2 = tid + 512, j3 = tid + 768;
    const bool p3 = (j3 < NNZ);

    // ---- front-batched index loads (independent, coalesced) ----
    int c0 = sc[j0];
    int c1 = sc[j1];
    int c2 = sc[j2];
    int c3 = p3 ? sc[j3] : 0;

    // ---- contiguous value streams (independent, coalesced) ----
    float s0 = sv[j0], s1 = sv[j1], s2 = sv[j2], s3 = p3 ? sv[j3] : 0.0f;
    float d0 = iv[j0], d1 = iv[j1], d2 = iv[j2], d3 = p3 ? iv[j3] : 0.0f;

    // ---- 4 independent scattered gathers in flight ----
    float g0 = lp[c0];
    float g1 = lp[c1];
    float g2 = lp[c2];
    float g3 = p3 ? lp[c3] : 0.0f;

    // ---- math ----
    float v0 = __expf(__expf((s0 - 1.0f - TAU * RARE * d0) * inv_tau) * inv_tau);
    float v1 = __expf(__expf((s1 - 1.0f - TAU * RARE * d1) * inv_tau) * inv_tau);
    float v2 = __expf(__expf((s2 - 1.0f - TAU * RARE * d2) * inv_tau) * inv_tau);
    float v3 = p3 ? __expf(__expf((s3 - 1.0f - TAU * RARE * d3) * inv_tau) * inv_tau) : 0.0f;

    float sum_v  = (v0 + v1) + (v2 + v3);
    float sum_gv = (v0 * g0 + v1 * g1) + (v2 * g2 + v3 * g3);

    // -------- block reduction of (sum_v, sum_gv) --------
    #pragma unroll
    for (int o = 16; o > 0; o >>= 1) {
        sum_v  += __shfl_down_sync(0xffffffffu, sum_v,  o);
        sum_gv += __shfl_down_sync(0xffffffffu, sum_gv, o);
    }
    __shared__ float s_v[8], s_gv[8];
    __shared__ bool  s_last;
    const int warp = tid >> 5;
    const int lane = tid & 31;
    if (lane == 0) { s_v[warp] = sum_v; s_gv[warp] = sum_gv; }
    __syncthreads();
    if (warp == 0) {
        float a = (lane < 8) ? s_v[lane]  : 0.0f;
        float b = (lane < 8) ? s_gv[lane] : 0.0f;
        #pragma unroll
        for (int o = 4; o > 0; o >>= 1) {
            a += __shfl_down_sync(0xffffffffu, a, o);
            b += __shfl_down_sync(0xffffffffu, b, o);
        }
        if (lane == 0) {
            float m = mask[n];
            g_smooth[n] = b / a;                        // sum(g * sim) for row n
            g_ml[n]     = lp[r] * m;                    // lp[n, target[n]] * m[n]
            g_maskv[n]  = m;
            __threadfence();                            // make partials visible
            unsigned int old = atomicAdd(&g_count, 1u);
            s_last = (old == (unsigned int)(gridDim.x - 1));
        }
    }
    __syncthreads();

    // -------- last CTA performs the final (deterministic) reduction --------
    if (s_last) {
        double d_sm = 0.0, d_ml = 0.0, d_m = 0.0;
        for (int i = tid; i < NROWS; i += 256) {
            d_sm += (double)g_smooth[i];
            d_ml += (double)g_ml[i];
            d_m  += (double)g_maskv[i];
        }
        #pragma unroll
        for (int o = 16; o > 0; o >>= 1) {
            d_sm += __shfl_down_sync(0xffffffffu, d_sm, o);
            d_ml += __shfl_down_sync(0xffffffffu, d_ml, o);
            d_m  += __shfl_down_sync(0xffffffffu, d_m,  o);
        }
        __shared__ double sh[3][8];
        if (lane == 0) { sh[0][warp] = d_sm; sh[1][warp] = d_ml; sh[2][warp] = d_m; }
        __syncthreads();
        if (warp == 0) {
            d_sm = (lane < 8) ? sh[0][lane] : 0.0;
            d_ml = (lane < 8) ? sh[1][lane] : 0.0;
            d_m  = (lane < 8) ? sh[2][lane] : 0.0;
            #pragma unroll
            for (int o = 4; o > 0; o >>= 1) {
                d_sm += __shfl_down_sync(0xffffffffu, d_sm, o);
                d_ml += __shfl_down_sync(0xffffffffu, d_ml, o);
                d_m  += __shfl_down_sync(0xffffffffu, d_m,  o);
            }
            if (lane == 0) {
                double smooth_loss = -d_sm / d_m;
                double ml_loss     = -d_ml / d_m;
                out[0] = (float)((double)ALPHA * smooth_loss
                                 + (1.0 - (double)ALPHA) * ml_loss);
                g_count = 0;   // reset for next graph replay
            }
        }
    }
}

// ---------------------------------------------------------------------------
extern "C" void kernel_launch(void* const* d_in, const int* in_sizes, int n_in,
                              void* d_out, int out_size)
{
    const float* logp       = (const float*)d_in[0];
    const float* mask       = (const float*)d_in[1];
    const float* sim_values = (const float*)d_in[2];
    const float* idf_values = (const float*)d_in[3];
    const int*   target     = (const int*)  d_in[4];
    const int*   sim_cols   = (const int*)  d_in[5];
    float*       out        = (float*)d_out;

    ws_fused_kernel<<<NROWS, 256>>>(logp, mask, sim_values, idf_values,
                                    target, sim_cols, out);
}